// round 14
// baseline (speedup 1.0000x reference)
#include <cuda_runtime.h>
#include <cuda_bf16.h>
#include <cstdint>

#define BATCH 8
#define LSEQ  1024
#define QK_SCALE 0.125f

// ---------------- scratch (no allocs allowed) ----------------
__device__ __nv_bfloat16 g_hn [(size_t)BATCH*512*LSEQ];    // [b][c][L]
__device__ __nv_bfloat16 g_qkv[(size_t)BATCH*1536*LSEQ];   // rows 0-511 q*s, 512-1023 k*s, 1024-1535 v
__device__ __nv_bfloat16 g_att[(size_t)BATCH*512*LSEQ];    // [b][inner][L]
__device__ __nv_bfloat16 g_w  [(size_t)2048*512];          // bf16 weights: Wq | Wkv | Wo

// ---------------- helpers ----------------
__device__ __forceinline__ uint32_t s2u(const void* p){
    uint32_t a;
    asm("{ .reg .u64 t; cvta.to.shared.u64 t, %1; cvt.u32.u64 %0, t; }" : "=r"(a) : "l"(p));
    return a;
}
__device__ __forceinline__ void ldm4(uint32_t* r, uint32_t a){
    asm volatile("ldmatrix.sync.aligned.m8n8.x4.shared.b16 {%0,%1,%2,%3}, [%4];"
        : "=r"(r[0]),"=r"(r[1]),"=r"(r[2]),"=r"(r[3]) : "r"(a));
}
__device__ __forceinline__ void ldm4t(uint32_t* r, uint32_t a){
    asm volatile("ldmatrix.sync.aligned.m8n8.x4.trans.shared.b16 {%0,%1,%2,%3}, [%4];"
        : "=r"(r[0]),"=r"(r[1]),"=r"(r[2]),"=r"(r[3]) : "r"(a));
}
__device__ __forceinline__ void mma16(float* d, const uint32_t* a, uint32_t b0, uint32_t b1){
    asm volatile("mma.sync.aligned.m16n8k16.row.col.f32.bf16.bf16.f32 "
        "{%0,%1,%2,%3}, {%4,%5,%6,%7}, {%8,%9}, {%0,%1,%2,%3};"
        : "+f"(d[0]),"+f"(d[1]),"+f"(d[2]),"+f"(d[3])
        : "r"(a[0]),"r"(a[1]),"r"(a[2]),"r"(a[3]), "r"(b0),"r"(b1));
}
__device__ __forceinline__ uint32_t bfp(float x, float y){
    __nv_bfloat162 t = __floats2bfloat162_rn(x, y);
    return *(uint32_t*)&t;
}
#define CPAu(s, g)  asm volatile("cp.async.cg.shared.global [%0], [%1], 16;" :: "r"(s), "l"(g))
#define CPCOMMIT()  asm volatile("cp.async.commit_group;" ::: "memory")
#define CPWAIT(n)   asm volatile("cp.async.wait_group %0;" :: "n"(n) : "memory")

// ---------------- 0) weight prep: fp32 -> bf16 ----------------
__global__ __launch_bounds__(256) void prep_kernel(const float* __restrict__ Wq,
    const float* __restrict__ Wkv, const float* __restrict__ Wo,
    __nv_bfloat16* __restrict__ w)
{
    const size_t off = ((size_t)blockIdx.x * 256 + threadIdx.x) * 4;
    const float* src;
    if (off < (size_t)512 * 512)            src = Wq + off;
    else if (off < (size_t)1536 * 512)      src = Wkv + (off - (size_t)512 * 512);
    else                                    src = Wo + (off - (size_t)1536 * 512);
    float4 v = *(const float4*)src;
    *(uint2*)(w + off) = make_uint2(bfp(v.x, v.y), bfp(v.z, v.w));
}

// ---------------- 1) GroupNorm (one-pass, smem-cached) -> bf16 hn[b][c][L] ----------------
__global__ __launch_bounds__(256) void gn_kernel(const float* __restrict__ x,
    const float* __restrict__ gamma, const float* __restrict__ beta,
    __nv_bfloat16* __restrict__ hn)
{
    extern __shared__ float xs[];
    const int b = blockIdx.x >> 5, g = blockIdx.x & 31;
    const float* xp = x + ((size_t)b * 512 + g * 16) * LSEQ;
    __nv_bfloat16* hp = hn + ((size_t)b * 512 + g * 16) * LSEQ;
    float s1 = 0.f, s2 = 0.f;
    for (int e = threadIdx.x * 4; e < 16 * LSEQ; e += 1024) {
        float4 v = *(const float4*)(xp + e);
        *(float4*)(xs + e) = v;
        s1 += v.x + v.y + v.z + v.w;
        s2 += v.x * v.x + v.y * v.y + v.z * v.z + v.w * v.w;
    }
    __shared__ float r1[32], r2[32];
    #pragma unroll
    for (int o = 16; o > 0; o >>= 1) {
        s1 += __shfl_down_sync(~0u, s1, o); s2 += __shfl_down_sync(~0u, s2, o);
    }
    int wid = threadIdx.x >> 5, lid = threadIdx.x & 31;
    if (lid == 0) { r1[wid] = s1; r2[wid] = s2; }
    __syncthreads();
    if (wid == 0) {
        s1 = (lid < 8) ? r1[lid] : 0.f; s2 = (lid < 8) ? r2[lid] : 0.f;
        #pragma unroll
        for (int o = 4; o > 0; o >>= 1) {
            s1 += __shfl_down_sync(~0u, s1, o); s2 += __shfl_down_sync(~0u, s2, o);
        }
        if (lid == 0) { r1[0] = s1; r2[0] = s2; }
    }
    __syncthreads();
    const float mean = r1[0] * (1.f / 16384.f);
    const float rstd = rsqrtf(r2[0] * (1.f / 16384.f) - mean * mean + 1e-5f);
    for (int e = threadIdx.x * 4; e < 16 * LSEQ; e += 1024) {
        int c = g * 16 + (e >> 10);
        float ga = gamma[c] * rstd, be = beta[c] - mean * ga;
        float4 v = *(const float4*)(xs + e);
        *(uint2*)(hp + e) = make_uint2(bfp(v.x * ga + be, v.y * ga + be),
                                       bfp(v.z * ga + be, v.w * ga + be));
    }
}

// ---------------- 2/4) bf16 GEMM 128x128, 32x64 warp tile, k-chunk 64, 3-stage ----------------
// smem: A 3x18432 (stride 144B) | B 3x17408 = 107520 -> 2 CTAs/SM
#define G_ASZ  18432
#define G_BOFF 55296
#define G_BSZ  17408
template<int MODE>
__global__ __launch_bounds__(256, 2) void gemm_mma(
    const __nv_bfloat16* __restrict__ Wall,
    const float* __restrict__ b0v, const float* __restrict__ b1v,
    const __nv_bfloat16* __restrict__ Bg, const float* __restrict__ xres,
    void* __restrict__ Cout)
{
    extern __shared__ unsigned char gsm[];
    const uint32_t sb = s2u(gsm);
    const int tid = threadIdx.x, lane = tid & 31, wid = tid >> 5;
    const int wm = wid & 3, wn = wid >> 2;
    const int n0 = blockIdx.x * 128, m0 = blockIdx.y * 128, b = blockIdx.z;

    const __nv_bfloat16* A;
    const float* bias;
    if (MODE == 0) {
        A = Wall + (size_t)m0 * 512;
        bias = (m0 < 512) ? (b0v + m0) : (b1v + (m0 - 512));
    } else {
        A = Wall + (size_t)(1536 + m0) * 512;
        bias = b0v + m0;
    }
    const __nv_bfloat16* Bb = Bg + (size_t)b * 512 * 1024 + n0;

    float acc[2][8][4];
    #pragma unroll
    for (int mt = 0; mt < 2; mt++)
        #pragma unroll
        for (int nt = 0; nt < 8; nt++)
            #pragma unroll
            for (int r = 0; r < 4; r++) acc[mt][nt][r] = 0.f;

    // fills: A rows 0-127 x 64k (4 cpa/thread), B 64k x 128n (4 cpa/thread)
    const int ae_r = tid >> 1, ae_c = (tid & 1) * 32;
    const int be_k = tid >> 2, be_c = (tid & 3) * 32;
    const uint32_t afill = sb + ae_r * 144 + ae_c * 2;
    const uint32_t bfill = sb + G_BOFF + be_k * 272 + be_c * 2;
    const __nv_bfloat16* agp = A + (size_t)ae_r * 512 + ae_c;
    const __nv_bfloat16* bgp = Bb + (size_t)be_k * 1024 + be_c;

    #define FILL(st, kc) do { \
        CPAu(afill + (st) * G_ASZ,      agp + (kc)); \
        CPAu(afill + (st) * G_ASZ + 16, agp + (kc) + 8); \
        CPAu(afill + (st) * G_ASZ + 32, agp + (kc) + 16); \
        CPAu(afill + (st) * G_ASZ + 48, agp + (kc) + 24); \
        CPAu(bfill + (st) * G_BSZ,      bgp + (size_t)(kc) * 1024); \
        CPAu(bfill + (st) * G_BSZ + 16, bgp + (size_t)(kc) * 1024 + 8); \
        CPAu(bfill + (st) * G_BSZ + 32, bgp + (size_t)(kc) * 1024 + 16); \
        CPAu(bfill + (st) * G_BSZ + 48, bgp + (size_t)(kc) * 1024 + 24); \
        CPCOMMIT(); } while (0)

    const uint32_t afrag = sb + (wm*32 + ((lane>>3)&1)*8 + (lane&7)) * 144 + ((lane>>4)*8) * 2;
    const uint32_t bfrag = sb + G_BOFF + (((lane>>3)&1)*8 + (lane&7)) * 272 + (wn*64 + (lane>>4)*8) * 2;

    FILL(0, 0); FILL(1, 64);
    #pragma unroll 1
    for (int i = 0; i < 8; i++) {
        const int st = i - (i / 3) * 3;
        if (i < 7) CPWAIT(1); else CPWAIT(0);
        __syncthreads();
        if (i + 2 < 8) {
            const int st2 = (i + 2) - ((i + 2) / 3) * 3;
            FILL(st2, (i + 2) * 64);
        }
        const uint32_t aoff = afrag + st * G_ASZ, boff = bfrag + st * G_BSZ;
        #pragma unroll
        for (int ks = 0; ks < 4; ks++) {
            const int kk = ks * 16;
            uint32_t af[2][4];
            #pragma unroll
            for (int mt = 0; mt < 2; mt++)
                ldm4(af[mt], aoff + mt * (16 * 144) + kk * 2);
            uint32_t bf_[4][4];
            #pragma unroll
            for (int j4 = 0; j4 < 4; j4++)
                ldm4t(bf_[j4], boff + kk * 272 + j4 * 32);
            #pragma unroll
            for (int nt = 0; nt < 8; nt++) {
                uint32_t b0 = bf_[nt>>1][(nt&1)*2], b1 = bf_[nt>>1][(nt&1)*2 + 1];
                mma16(acc[0][nt], af[0], b0, b1);
                mma16(acc[1][nt], af[1], b0, b1);
            }
        }
        __syncthreads();
    }

    const float sc = (MODE == 0 && m0 < 1024) ? QK_SCALE : 1.0f;
    #pragma unroll
    for (int mt = 0; mt < 2; mt++) {
        const int loc = wm * 32 + mt * 16 + (lane >> 2);
        const int m = m0 + loc;
        const float bi0 = bias[loc], bi1 = bias[loc + 8];
        #pragma unroll
        for (int nt = 0; nt < 8; nt++) {
            const int nc = wn * 64 + nt * 8 + 2 * (lane & 3);
            float v00 = (acc[mt][nt][0] + bi0) * sc, v01 = (acc[mt][nt][1] + bi0) * sc;
            float v10 = (acc[mt][nt][2] + bi1) * sc, v11 = (acc[mt][nt][3] + bi1) * sc;
            if (MODE == 0) {
                __nv_bfloat16* row0 = (__nv_bfloat16*)Cout + ((size_t)b * 1536 + m) * 1024 + n0 + nc;
                *(uint32_t*)row0              = bfp(v00, v01);
                *(uint32_t*)(row0 + 8 * 1024) = bfp(v10, v11);
            } else {
                float* row0 = (float*)Cout + ((size_t)b * 512 + m) * 1024 + n0 + nc;
                const float* xr0 = xres + ((size_t)b * 512 + m) * 1024 + n0 + nc;
                float2 x0 = *(const float2*)xr0, x1 = *(const float2*)(xr0 + 8 * 1024);
                *(float2*)row0              = make_float2(v00 + x0.x, v01 + x0.y);
                *(float2*)(row0 + 8 * 1024) = make_float2(v10 + x1.x, v11 + x1.y);
            }
        }
    }
    #undef FILL
}

// ---------------- 3) FA2 attention: m32 warp tile, 256 q-rows/CTA (round-11 proven) ----------------
// smem: K bufs at 0/17408/34816, V bufs at 52224/69632/87040 = 104448; Q (33792B) overlays K bufs 0-1.
#define A_VOFF 52224
#define ONES2  0x3F803F80u
__global__ __launch_bounds__(256, 1) void attn_mma(const __nv_bfloat16* __restrict__ qkv,
                                                   __nv_bfloat16* __restrict__ att)
{
    extern __shared__ unsigned char dsm[];
    const uint32_t sb = s2u(dsm);
    const int tid = threadIdx.x, lane = tid & 31, wid = tid >> 5;
    const int b = blockIdx.z, h = blockIdx.y, q0 = blockIdx.x * 256;

    const __nv_bfloat16* Qg = qkv + ((size_t)b * 1536 + h * 64) * 1024 + q0;
    const __nv_bfloat16* Kg = qkv + ((size_t)b * 1536 + 512 + h * 64) * 1024;
    const __nv_bfloat16* Vg = qkv + ((size_t)b * 1536 + 1024 + h * 64) * 1024;

    __nv_bfloat16* Qs = (__nv_bfloat16*)dsm;
    #pragma unroll
    for (int it = 0; it < 8; it++) {
        int idx = tid + it * 256, d = idx >> 5, c8 = (idx & 31) * 8;
        *(uint4*)(Qs + d * 264 + c8) = *(const uint4*)(Qg + (size_t)d * 1024 + c8);
    }
    __syncthreads();
    uint32_t qf[4][2][4];
    #pragma unroll
    for (int ks = 0; ks < 4; ks++)
        #pragma unroll
        for (int mt = 0; mt < 2; mt++)
            ldm4t(qf[ks][mt], sb + (ks*16 + (lane>>4)*8 + (lane&7)) * 528
                                 + (wid*32 + mt*16 + ((lane>>3)&1)*8) * 2);
    __syncthreads();

    const int fd = tid >> 2, fc = (tid & 3) * 32;
    const uint32_t kfill = sb + fd * 272 + fc * 2;
    const uint32_t vfill = sb + A_VOFF + fd * 272 + fc * 2;
    const __nv_bfloat16* kgp = Kg + (size_t)fd * 1024 + fc;
    const __nv_bfloat16* vgp = Vg + (size_t)fd * 1024 + fc;
    #define FILLKV(stoff, s0) do { \
        _Pragma("unroll") \
        for (int j = 0; j < 4; j++) { \
            CPAu(kfill + (stoff) + j * 16, kgp + (s0) + j * 8); \
            CPAu(vfill + (stoff) + j * 16, vgp + (s0) + j * 8); } \
        CPCOMMIT(); } while (0)

    const uint32_t kfrag = sb + (((lane>>3)&1)*8 + (lane&7)) * 272 + ((lane>>4)*8) * 2;
    const uint32_t vfrag = sb + A_VOFF + ((lane>>4)*8 + (lane&7)) * 272 + (((lane>>3)&1)*8) * 2;

    float o_acc[2][8][4];
    #pragma unroll
    for (int mt = 0; mt < 2; mt++)
        #pragma unroll
        for (int nt = 0; nt < 8; nt++)
            #pragma unroll
            for (int r = 0; r < 4; r++) o_acc[mt][nt][r] = 0.f;
    float sum_acc[2][4] = {{0.f,0.f,0.f,0.f},{0.f,0.f,0.f,0.f}};

    FILLKV(0, 0); FILLKV(17408, 128);
    #pragma unroll 1
    for (int ck = 0; ck < 8; ck++) {
        const int st = ck - (ck / 3) * 3;
        if (ck < 7) CPWAIT(1); else CPWAIT(0);
        __syncthreads();
        if (ck + 2 < 8) {
            const int st2 = (ck + 2) - ((ck + 2) / 3) * 3;
            FILLKV(st2 * 17408, (ck + 2) * 128);
        }
        const uint32_t koff = kfrag + st * 17408, voff = vfrag + st * 17408;

        #pragma unroll
        for (int qt = 0; qt < 4; qt++) {
            const int nb = qt * 32;
            float s_acc[2][4][4];
            #pragma unroll
            for (int mt = 0; mt < 2; mt++)
                #pragma unroll
                for (int nt = 0; nt < 4; nt++)
                    #pragma unroll
                    for (int r = 0; r < 4; r++) s_acc[mt][nt][r] = 0.f;
            #pragma unroll
            for (int ks = 0; ks < 4; ks++) {
                uint32_t kf[2][4];
                #pragma unroll
                for (int j4 = 0; j4 < 2; j4++)
                    ldm4t(kf[j4], koff + ks * (16 * 272) + (nb + j4 * 16) * 2);
                #pragma unroll
                for (int nt = 0; nt < 4; nt++) {
                    uint32_t b0 = kf[nt>>1][(nt&1)*2], b1 = kf[nt>>1][(nt&1)*2 + 1];
                    mma16(s_acc[0][nt], qf[ks][0], b0, b1);
                    mma16(s_acc[1][nt], qf[ks][1], b0, b1);
                }
            }
            uint32_t pf[2][2][4];
            #pragma unroll
            for (int mt = 0; mt < 2; mt++)
                #pragma unroll
                for (int j = 0; j < 2; j++) {
                    float e0 = __expf(s_acc[mt][2*j][0]),   e1 = __expf(s_acc[mt][2*j][1]);
                    float e2 = __expf(s_acc[mt][2*j][2]),   e3 = __expf(s_acc[mt][2*j][3]);
                    float f0 = __expf(s_acc[mt][2*j+1][0]), f1 = __expf(s_acc[mt][2*j+1][1]);
                    float f2 = __expf(s_acc[mt][2*j+1][2]), f3 = __expf(s_acc[mt][2*j+1][3]);
                    pf[mt][j][0] = bfp(e0, e1); pf[mt][j][1] = bfp(e2, e3);
                    pf[mt][j][2] = bfp(f0, f1); pf[mt][j][3] = bfp(f2, f3);
                }
            #pragma unroll
            for (int j = 0; j < 2; j++) {
                const int kk = nb + j * 16;
                uint32_t vb[4][4];
                #pragma unroll
                for (int j4 = 0; j4 < 4; j4++)
                    ldm4(vb[j4], voff + j4 * (16 * 272) + kk * 2);
                #pragma unroll
                for (int nt = 0; nt < 8; nt++) {
                    uint32_t b0 = vb[nt>>1][(nt&1)*2], b1 = vb[nt>>1][(nt&1)*2 + 1];
                    mma16(o_acc[0][nt], pf[0][j], b0, b1);
                    mma16(o_acc[1][nt], pf[1][j], b0, b1);
                }
                mma16(sum_acc[0], pf[0][j], ONES2, ONES2);
                mma16(sum_acc[1], pf[1][j], ONES2, ONES2);
            }
        }
    }

    const float il0 = 1.f / sum_acc[0][0], ih0 = 1.f / sum_acc[0][2];
    const float il1 = 1.f / sum_acc[1][0], ih1 = 1.f / sum_acc[1][2];

    __syncthreads();
    float* Osm = (float*)dsm;
    #pragma unroll
    for (int mt = 0; mt < 2; mt++) {
        const int rl = wid * 32 + mt * 16 + (lane >> 2);
        const float il = mt ? il1 : il0, ih = mt ? ih1 : ih0;
        #pragma unroll
        for (int nt = 0; nt < 8; nt++) {
            const int d = nt * 8 + 2 * (lane & 3);
            Osm[(size_t)d * 264 + rl]           = o_acc[mt][nt][0] * il;
            Osm[(size_t)(d + 1) * 264 + rl]     = o_acc[mt][nt][1] * il;
            Osm[(size_t)d * 264 + rl + 8]       = o_acc[mt][nt][2] * ih;
            Osm[(size_t)(d + 1) * 264 + rl + 8] = o_acc[mt][nt][3] * ih;
        }
    }
    __syncthreads();
    __nv_bfloat16* Og = att + ((size_t)b * 512 + h * 64) * 1024 + q0;
    #pragma unroll
    for (int it = 0; it < 16; it++) {
        int idx = tid + it * 256, d = idx >> 6, t4 = (idx & 63) * 4;
        const float* src = Osm + (size_t)d * 264 + t4;
        *(uint2*)(Og + (size_t)d * 1024 + t4) = make_uint2(bfp(src[0], src[1]), bfp(src[2], src[3]));
    }
    #undef FILLKV
}

// ---------------- launch ----------------
extern "C" void kernel_launch(void* const* d_in, const int* in_sizes, int n_in,
                              void* d_out, int out_size)
{
    const float* x     = (const float*)d_in[0];
    const float* gamma = (const float*)d_in[1];
    const float* beta  = (const float*)d_in[2];
    const float* Wq    = (const float*)d_in[3];
    const float* bq    = (const float*)d_in[4];
    const float* Wkv   = (const float*)d_in[5];
    const float* bkv   = (const float*)d_in[6];
    const float* Wo    = (const float*)d_in[7];
    const float* bo    = (const float*)d_in[8];

    __nv_bfloat16* hn;  cudaGetSymbolAddress((void**)&hn,  g_hn);
    __nv_bfloat16* qkv; cudaGetSymbolAddress((void**)&qkv, g_qkv);
    __nv_bfloat16* att; cudaGetSymbolAddress((void**)&att, g_att);
    __nv_bfloat16* w;   cudaGetSymbolAddress((void**)&w,   g_w);

    prep_kernel<<<1024, 256>>>(Wq, Wkv, Wo, w);
    {
        cudaFuncSetAttribute(gn_kernel, cudaFuncAttributeMaxDynamicSharedMemorySize, 65536);
        gn_kernel<<<256, 256, 65536>>>(x, gamma, beta, hn);
    }
    {
        cudaFuncSetAttribute(gemm_mma<0>, cudaFuncAttributeMaxDynamicSharedMemorySize, 107520);
        dim3 grid(8, 12, BATCH);
        gemm_mma<0><<<grid, 256, 107520>>>(w, bq, bkv, hn, nullptr, qkv);
    }
    {
        cudaFuncSetAttribute(attn_mma, cudaFuncAttributeMaxDynamicSharedMemorySize, 104448);
        dim3 grid(4, 8, BATCH);
        attn_mma<<<grid, 256, 104448>>>(qkv, att);
    }
    {
        cudaFuncSetAttribute(gemm_mma<1>, cudaFuncAttributeMaxDynamicSharedMemorySize, 107520);
        dim3 grid(8, 4, BATCH);
        gemm_mma<1><<<grid, 256, 107520>>>(w, bo, nullptr, att, x, d_out);
    }
}

// round 15
// speedup vs baseline: 1.1684x; 1.1684x over previous
#include <cuda_runtime.h>
#include <cuda_bf16.h>
#include <cstdint>

#define BATCH 8
#define LSEQ  1024
#define QK_SCALE 0.125f

// ---------------- scratch (no allocs allowed) ----------------
__device__ __nv_bfloat16 g_hn [(size_t)BATCH*512*LSEQ];    // [b][c][L]
__device__ __nv_bfloat16 g_qkv[(size_t)BATCH*1536*LSEQ];   // rows 0-511 q*s, 512-1023 k*s, 1024-1535 v
__device__ __nv_bfloat16 g_att[(size_t)BATCH*512*LSEQ];    // [b][inner][L]
__device__ __nv_bfloat16 g_w  [(size_t)2048*512];          // bf16 weights: Wq | Wkv | Wo

// ---------------- helpers ----------------
__device__ __forceinline__ uint32_t s2u(const void* p){
    uint32_t a;
    asm("{ .reg .u64 t; cvta.to.shared.u64 t, %1; cvt.u32.u64 %0, t; }" : "=r"(a) : "l"(p));
    return a;
}
__device__ __forceinline__ void ldm4(uint32_t* r, uint32_t a){
    asm volatile("ldmatrix.sync.aligned.m8n8.x4.shared.b16 {%0,%1,%2,%3}, [%4];"
        : "=r"(r[0]),"=r"(r[1]),"=r"(r[2]),"=r"(r[3]) : "r"(a));
}
__device__ __forceinline__ void ldm4t(uint32_t* r, uint32_t a){
    asm volatile("ldmatrix.sync.aligned.m8n8.x4.trans.shared.b16 {%0,%1,%2,%3}, [%4];"
        : "=r"(r[0]),"=r"(r[1]),"=r"(r[2]),"=r"(r[3]) : "r"(a));
}
__device__ __forceinline__ void mma16(float* d, const uint32_t* a, uint32_t b0, uint32_t b1){
    asm volatile("mma.sync.aligned.m16n8k16.row.col.f32.bf16.bf16.f32 "
        "{%0,%1,%2,%3}, {%4,%5,%6,%7}, {%8,%9}, {%0,%1,%2,%3};"
        : "+f"(d[0]),"+f"(d[1]),"+f"(d[2]),"+f"(d[3])
        : "r"(a[0]),"r"(a[1]),"r"(a[2]),"r"(a[3]), "r"(b0),"r"(b1));
}
__device__ __forceinline__ uint32_t bfp(float x, float y){
    __nv_bfloat162 t = __floats2bfloat162_rn(x, y);
    return *(uint32_t*)&t;
}
#define CPAu(s, g)  asm volatile("cp.async.cg.shared.global [%0], [%1], 16;" :: "r"(s), "l"(g))
#define CPCOMMIT()  asm volatile("cp.async.commit_group;" ::: "memory")
#define CPWAIT(n)   asm volatile("cp.async.wait_group %0;" :: "n"(n) : "memory")

// ---------------- 1) fused: GroupNorm (blocks 0-255) + weight prep (blocks 256-1279) ----------------
__global__ __launch_bounds__(256) void gn_prep_kernel(const float* __restrict__ x,
    const float* __restrict__ gamma, const float* __restrict__ beta,
    __nv_bfloat16* __restrict__ hn,
    const float* __restrict__ Wq, const float* __restrict__ Wkv,
    const float* __restrict__ Wo, __nv_bfloat16* __restrict__ w)
{
    if (blockIdx.x >= 256) {
        // weight prep: fp32 -> bf16 (1024 blocks x 256 threads x 4 elems)
        const size_t off = ((size_t)(blockIdx.x - 256) * 256 + threadIdx.x) * 4;
        const float* src;
        if (off < (size_t)512 * 512)       src = Wq + off;
        else if (off < (size_t)1536 * 512) src = Wkv + (off - (size_t)512 * 512);
        else                               src = Wo + (off - (size_t)1536 * 512);
        float4 v = *(const float4*)src;
        *(uint2*)(w + off) = make_uint2(bfp(v.x, v.y), bfp(v.z, v.w));
        return;
    }
    extern __shared__ float xs[];
    const int b = blockIdx.x >> 5, g = blockIdx.x & 31;
    const float* xp = x + ((size_t)b * 512 + g * 16) * LSEQ;
    __nv_bfloat16* hp = hn + ((size_t)b * 512 + g * 16) * LSEQ;
    float s1 = 0.f, s2 = 0.f;
    for (int e = threadIdx.x * 4; e < 16 * LSEQ; e += 1024) {
        float4 v = *(const float4*)(xp + e);
        *(float4*)(xs + e) = v;
        s1 += v.x + v.y + v.z + v.w;
        s2 += v.x * v.x + v.y * v.y + v.z * v.z + v.w * v.w;
    }
    __shared__ float r1[32], r2[32];
    #pragma unroll
    for (int o = 16; o > 0; o >>= 1) {
        s1 += __shfl_down_sync(~0u, s1, o); s2 += __shfl_down_sync(~0u, s2, o);
    }
    int wid = threadIdx.x >> 5, lid = threadIdx.x & 31;
    if (lid == 0) { r1[wid] = s1; r2[wid] = s2; }
    __syncthreads();
    if (wid == 0) {
        s1 = (lid < 8) ? r1[lid] : 0.f; s2 = (lid < 8) ? r2[lid] : 0.f;
        #pragma unroll
        for (int o = 4; o > 0; o >>= 1) {
            s1 += __shfl_down_sync(~0u, s1, o); s2 += __shfl_down_sync(~0u, s2, o);
        }
        if (lid == 0) { r1[0] = s1; r2[0] = s2; }
    }
    __syncthreads();
    const float mean = r1[0] * (1.f / 16384.f);
    const float rstd = rsqrtf(r2[0] * (1.f / 16384.f) - mean * mean + 1e-5f);
    for (int e = threadIdx.x * 4; e < 16 * LSEQ; e += 1024) {
        int c = g * 16 + (e >> 10);
        float ga = gamma[c] * rstd, be = beta[c] - mean * ga;
        float4 v = *(const float4*)(xs + e);
        *(uint2*)(hp + e) = make_uint2(bfp(v.x * ga + be, v.y * ga + be),
                                       bfp(v.z * ga + be, v.w * ga + be));
    }
}

// ---------------- 2/4) bf16 GEMM 128x128, 32x64 warp tile, 3-stage cp.async (R11 exact) ----------------
// smem: A 3x10240 | B 3x8704 = 56832
#define G_BOFF 30720
template<int MODE>
__global__ __launch_bounds__(256, 2) void gemm_mma(
    const __nv_bfloat16* __restrict__ Wall,
    const float* __restrict__ b0v, const float* __restrict__ b1v,
    const __nv_bfloat16* __restrict__ Bg, const float* __restrict__ xres,
    void* __restrict__ Cout)
{
    extern __shared__ unsigned char gsm[];
    const uint32_t sb = s2u(gsm);
    const int tid = threadIdx.x, lane = tid & 31, wid = tid >> 5;
    const int wm = wid & 3, wn = wid >> 2;
    const int n0 = blockIdx.x * 128, m0 = blockIdx.y * 128, b = blockIdx.z;

    const __nv_bfloat16* A;
    const float* bias;
    if (MODE == 0) {
        A = Wall + (size_t)m0 * 512;
        bias = (m0 < 512) ? (b0v + m0) : (b1v + (m0 - 512));
    } else {
        A = Wall + (size_t)(1536 + m0) * 512;
        bias = b0v + m0;
    }
    const __nv_bfloat16* Bb = Bg + (size_t)b * 512 * 1024 + n0;

    float acc[2][8][4];
    #pragma unroll
    for (int mt = 0; mt < 2; mt++)
        #pragma unroll
        for (int nt = 0; nt < 8; nt++)
            #pragma unroll
            for (int r = 0; r < 4; r++) acc[mt][nt][r] = 0.f;

    const int ae_r = tid >> 1, ae_c = (tid & 1) * 16;
    const int be_k = tid >> 3, be_c = (tid & 7) * 16;
    const uint32_t afill = sb + ae_r * 80 + ae_c * 2;
    const uint32_t bfill = sb + G_BOFF + be_k * 272 + be_c * 2;
    const __nv_bfloat16* agp = A + (size_t)ae_r * 512 + ae_c;
    const __nv_bfloat16* bgp = Bb + (size_t)be_k * 1024 + be_c;

    #define FILL(st, kc) do { \
        CPAu(afill + (st) * 10240,      agp + (kc)); \
        CPAu(afill + (st) * 10240 + 16, agp + (kc) + 8); \
        CPAu(bfill + (st) * 8704,       bgp + (size_t)(kc) * 1024); \
        CPAu(bfill + (st) * 8704 + 16,  bgp + (size_t)(kc) * 1024 + 8); \
        CPCOMMIT(); } while (0)

    const uint32_t afrag = sb + (wm*32 + ((lane>>3)&1)*8 + (lane&7)) * 80 + ((lane>>4)*8) * 2;
    const uint32_t bfrag = sb + G_BOFF + (((lane>>3)&1)*8 + (lane&7)) * 272 + (wn*64 + (lane>>4)*8) * 2;

    FILL(0, 0); FILL(1, 32);
    #pragma unroll 1
    for (int i = 0; i < 16; i++) {
        const int st = i - (i / 3) * 3;
        if (i < 15) CPWAIT(1); else CPWAIT(0);
        __syncthreads();
        if (i + 2 < 16) {
            const int st2 = (i + 2) - ((i + 2) / 3) * 3;
            FILL(st2, (i + 2) * 32);
        }
        const uint32_t aoff = afrag + st * 10240, boff = bfrag + st * 8704;
        #pragma unroll
        for (int ks = 0; ks < 2; ks++) {
            const int kk = ks * 16;
            uint32_t af[2][4];
            #pragma unroll
            for (int mt = 0; mt < 2; mt++)
                ldm4(af[mt], aoff + mt * (16 * 80) + kk * 2);
            uint32_t bf_[4][4];
            #pragma unroll
            for (int j4 = 0; j4 < 4; j4++)
                ldm4t(bf_[j4], boff + kk * 272 + j4 * 32);
            #pragma unroll
            for (int nt = 0; nt < 8; nt++) {
                uint32_t b0 = bf_[nt>>1][(nt&1)*2], b1 = bf_[nt>>1][(nt&1)*2 + 1];
                mma16(acc[0][nt], af[0], b0, b1);
                mma16(acc[1][nt], af[1], b0, b1);
            }
        }
    }

    const float sc = (MODE == 0 && m0 < 1024) ? QK_SCALE : 1.0f;
    #pragma unroll
    for (int mt = 0; mt < 2; mt++) {
        const int loc = wm * 32 + mt * 16 + (lane >> 2);
        const int m = m0 + loc;
        const float bi0 = bias[loc], bi1 = bias[loc + 8];
        #pragma unroll
        for (int nt = 0; nt < 8; nt++) {
            const int nc = wn * 64 + nt * 8 + 2 * (lane & 3);
            float v00 = (acc[mt][nt][0] + bi0) * sc, v01 = (acc[mt][nt][1] + bi0) * sc;
            float v10 = (acc[mt][nt][2] + bi1) * sc, v11 = (acc[mt][nt][3] + bi1) * sc;
            if (MODE == 0) {
                __nv_bfloat16* row0 = (__nv_bfloat16*)Cout + ((size_t)b * 1536 + m) * 1024 + n0 + nc;
                *(uint32_t*)row0              = bfp(v00, v01);
                *(uint32_t*)(row0 + 8 * 1024) = bfp(v10, v11);
            } else {
                float* row0 = (float*)Cout + ((size_t)b * 512 + m) * 1024 + n0 + nc;
                const float* xr0 = xres + ((size_t)b * 512 + m) * 1024 + n0 + nc;
                float2 x0 = *(const float2*)xr0, x1 = *(const float2*)(xr0 + 8 * 1024);
                *(float2*)row0              = make_float2(v00 + x0.x, v01 + x0.y);
                *(float2*)(row0 + 8 * 1024) = make_float2(v10 + x1.x, v11 + x1.y);
            }
        }
    }
    #undef FILL
}

// ---------------- 3) FA2 attention: m32 warp tile, 256 q-rows/CTA (R11 exact) ----------------
// smem: K bufs at 0/17408/34816, V bufs at 52224/69632/87040 = 104448; Q (33792B) overlays K bufs 0-1.
#define A_VOFF 52224
#define ONES2  0x3F803F80u
__global__ __launch_bounds__(256, 1) void attn_mma(const __nv_bfloat16* __restrict__ qkv,
                                                   __nv_bfloat16* __restrict__ att)
{
    extern __shared__ unsigned char dsm[];
    const uint32_t sb = s2u(dsm);
    const int tid = threadIdx.x, lane = tid & 31, wid = tid >> 5;
    const int b = blockIdx.z, h = blockIdx.y, q0 = blockIdx.x * 256;

    const __nv_bfloat16* Qg = qkv + ((size_t)b * 1536 + h * 64) * 1024 + q0;
    const __nv_bfloat16* Kg = qkv + ((size_t)b * 1536 + 512 + h * 64) * 1024;
    const __nv_bfloat16* Vg = qkv + ((size_t)b * 1536 + 1024 + h * 64) * 1024;

    __nv_bfloat16* Qs = (__nv_bfloat16*)dsm;
    #pragma unroll
    for (int it = 0; it < 8; it++) {
        int idx = tid + it * 256, d = idx >> 5, c8 = (idx & 31) * 8;
        *(uint4*)(Qs + d * 264 + c8) = *(const uint4*)(Qg + (size_t)d * 1024 + c8);
    }
    __syncthreads();
    uint32_t qf[4][2][4];
    #pragma unroll
    for (int ks = 0; ks < 4; ks++)
        #pragma unroll
        for (int mt = 0; mt < 2; mt++)
            ldm4t(qf[ks][mt], sb + (ks*16 + (lane>>4)*8 + (lane&7)) * 528
                                 + (wid*32 + mt*16 + ((lane>>3)&1)*8) * 2);
    __syncthreads();

    const int fd = tid >> 2, fc = (tid & 3) * 32;
    const uint32_t kfill = sb + fd * 272 + fc * 2;
    const uint32_t vfill = sb + A_VOFF + fd * 272 + fc * 2;
    const __nv_bfloat16* kgp = Kg + (size_t)fd * 1024 + fc;
    const __nv_bfloat16* vgp = Vg + (size_t)fd * 1024 + fc;
    #define FILLKV(stoff, s0) do { \
        _Pragma("unroll") \
        for (int j = 0; j < 4; j++) { \
            CPAu(kfill + (stoff) + j * 16, kgp + (s0) + j * 8); \
            CPAu(vfill + (stoff) + j * 16, vgp + (s0) + j * 8); } \
        CPCOMMIT(); } while (0)

    const uint32_t kfrag = sb + (((lane>>3)&1)*8 + (lane&7)) * 272 + ((lane>>4)*8) * 2;
    const uint32_t vfrag = sb + A_VOFF + ((lane>>4)*8 + (lane&7)) * 272 + (((lane>>3)&1)*8) * 2;

    float o_acc[2][8][4];
    #pragma unroll
    for (int mt = 0; mt < 2; mt++)
        #pragma unroll
        for (int nt = 0; nt < 8; nt++)
            #pragma unroll
            for (int r = 0; r < 4; r++) o_acc[mt][nt][r] = 0.f;
    float sum_acc[2][4] = {{0.f,0.f,0.f,0.f},{0.f,0.f,0.f,0.f}};

    FILLKV(0, 0); FILLKV(17408, 128);
    #pragma unroll 1
    for (int ck = 0; ck < 8; ck++) {
        const int st = ck - (ck / 3) * 3;
        if (ck < 7) CPWAIT(1); else CPWAIT(0);
        __syncthreads();
        if (ck + 2 < 8) {
            const int st2 = (ck + 2) - ((ck + 2) / 3) * 3;
            FILLKV(st2 * 17408, (ck + 2) * 128);
        }
        const uint32_t koff = kfrag + st * 17408, voff = vfrag + st * 17408;

        #pragma unroll
        for (int qt = 0; qt < 4; qt++) {
            const int nb = qt * 32;
            float s_acc[2][4][4];
            #pragma unroll
            for (int mt = 0; mt < 2; mt++)
                #pragma unroll
                for (int nt = 0; nt < 4; nt++)
                    #pragma unroll
                    for (int r = 0; r < 4; r++) s_acc[mt][nt][r] = 0.f;
            #pragma unroll
            for (int ks = 0; ks < 4; ks++) {
                uint32_t kf[2][4];
                #pragma unroll
                for (int j4 = 0; j4 < 2; j4++)
                    ldm4t(kf[j4], koff + ks * (16 * 272) + (nb + j4 * 16) * 2);
                #pragma unroll
                for (int nt = 0; nt < 4; nt++) {
                    uint32_t b0 = kf[nt>>1][(nt&1)*2], b1 = kf[nt>>1][(nt&1)*2 + 1];
                    mma16(s_acc[0][nt], qf[ks][0], b0, b1);
                    mma16(s_acc[1][nt], qf[ks][1], b0, b1);
                }
            }
            uint32_t pf[2][2][4];
            #pragma unroll
            for (int mt = 0; mt < 2; mt++)
                #pragma unroll
                for (int j = 0; j < 2; j++) {
                    float e0 = __expf(s_acc[mt][2*j][0]),   e1 = __expf(s_acc[mt][2*j][1]);
                    float e2 = __expf(s_acc[mt][2*j][2]),   e3 = __expf(s_acc[mt][2*j][3]);
                    float f0 = __expf(s_acc[mt][2*j+1][0]), f1 = __expf(s_acc[mt][2*j+1][1]);
                    float f2 = __expf(s_acc[mt][2*j+1][2]), f3 = __expf(s_acc[mt][2*j+1][3]);
                    pf[mt][j][0] = bfp(e0, e1); pf[mt][j][1] = bfp(e2, e3);
                    pf[mt][j][2] = bfp(f0, f1); pf[mt][j][3] = bfp(f2, f3);
                }
            #pragma unroll
            for (int j = 0; j < 2; j++) {
                const int kk = nb + j * 16;
                uint32_t vb[4][4];
                #pragma unroll
                for (int j4 = 0; j4 < 4; j4++)
                    ldm4(vb[j4], voff + j4 * (16 * 272) + kk * 2);
                #pragma unroll
                for (int nt = 0; nt < 8; nt++) {
                    uint32_t b0 = vb[nt>>1][(nt&1)*2], b1 = vb[nt>>1][(nt&1)*2 + 1];
                    mma16(o_acc[0][nt], pf[0][j], b0, b1);
                    mma16(o_acc[1][nt], pf[1][j], b0, b1);
                }
                mma16(sum_acc[0], pf[0][j], ONES2, ONES2);
                mma16(sum_acc[1], pf[1][j], ONES2, ONES2);
            }
        }
    }

    const float il0 = 1.f / sum_acc[0][0], ih0 = 1.f / sum_acc[0][2];
    const float il1 = 1.f / sum_acc[1][0], ih1 = 1.f / sum_acc[1][2];

    __syncthreads();
    float* Osm = (float*)dsm;
    #pragma unroll
    for (int mt = 0; mt < 2; mt++) {
        const int rl = wid * 32 + mt * 16 + (lane >> 2);
        const float il = mt ? il1 : il0, ih = mt ? ih1 : ih0;
        #pragma unroll
        for (int nt = 0; nt < 8; nt++) {
            const int d = nt * 8 + 2 * (lane & 3);
            Osm[(size_t)d * 264 + rl]           = o_acc[mt][nt][0] * il;
            Osm[(size_t)(d + 1) * 264 + rl]     = o_acc[mt][nt][1] * il;
            Osm[(size_t)d * 264 + rl + 8]       = o_acc[mt][nt][2] * ih;
            Osm[(size_t)(d + 1) * 264 + rl + 8] = o_acc[mt][nt][3] * ih;
        }
    }
    __syncthreads();
    __nv_bfloat16* Og = att + ((size_t)b * 512 + h * 64) * 1024 + q0;
    #pragma unroll
    for (int it = 0; it < 16; it++) {
        int idx = tid + it * 256, d = idx >> 6, t4 = (idx & 63) * 4;
        const float* src = Osm + (size_t)d * 264 + t4;
        *(uint2*)(Og + (size_t)d * 1024 + t4) = make_uint2(bfp(src[0], src[1]), bfp(src[2], src[3]));
    }
    #undef FILLKV
}

// ---------------- launch ----------------
extern "C" void kernel_launch(void* const* d_in, const int* in_sizes, int n_in,
                              void* d_out, int out_size)
{
    const float* x     = (const float*)d_in[0];
    const float* gamma = (const float*)d_in[1];
    const float* beta  = (const float*)d_in[2];
    const float* Wq    = (const float*)d_in[3];
    const float* bq    = (const float*)d_in[4];
    const float* Wkv   = (const float*)d_in[5];
    const float* bkv   = (const float*)d_in[6];
    const float* Wo    = (const float*)d_in[7];
    const float* bo    = (const float*)d_in[8];

    __nv_bfloat16* hn;  cudaGetSymbolAddress((void**)&hn,  g_hn);
    __nv_bfloat16* qkv; cudaGetSymbolAddress((void**)&qkv, g_qkv);
    __nv_bfloat16* att; cudaGetSymbolAddress((void**)&att, g_att);
    __nv_bfloat16* w;   cudaGetSymbolAddress((void**)&w,   g_w);

    {
        cudaFuncSetAttribute(gn_prep_kernel, cudaFuncAttributeMaxDynamicSharedMemorySize, 65536);
        gn_prep_kernel<<<1280, 256, 65536>>>(x, gamma, beta, hn, Wq, Wkv, Wo, w);
    }
    {
        cudaFuncSetAttribute(gemm_mma<0>, cudaFuncAttributeMaxDynamicSharedMemorySize, 56832);
        dim3 grid(8, 12, BATCH);
        gemm_mma<0><<<grid, 256, 56832>>>(w, bq, bkv, hn, nullptr, qkv);
    }
    {
        cudaFuncSetAttribute(attn_mma, cudaFuncAttributeMaxDynamicSharedMemorySize, 104448);
        dim3 grid(4, 8, BATCH);
        attn_mma<<<grid, 256, 104448>>>(qkv, att);
    }
    {
        cudaFuncSetAttribute(gemm_mma<1>, cudaFuncAttributeMaxDynamicSharedMemorySize, 56832);
        dim3 grid(8, 4, BATCH);
        gemm_mma<1><<<grid, 256, 56832>>>(w, bo, nullptr, att, x, d_out);
    }
}